// round 6
// baseline (speedup 1.0000x reference)
#include <cuda_runtime.h>
#include <cuda_bf16.h>
#include <cstdint>

#define N_NODES 50000
#define N_EDGES 800000
#define HIDDEN  128
#define H4      512
#define KC      64            // K elements per chunk
#define NCH     8             // 512 / 64
#define TILE_M  256
#define EDGE_BLOCKS (N_EDGES / TILE_M)   // 3125

#define ROWB    144                // padded bytes per 64-half tile row
#define A_OFF_H 0
#define A_OFF_L 36864              // 256*144
#define B_OFF_H 73728
#define B_OFF_L 92160              // +128*144
#define STAGE   110592
#define HEAD    4096
#define SMEM_BYTES (HEAD + 2 * STAGE)   // 225280

// Precomputed P = emb @ W1[:128] + b1, Q = emb @ W1[128:]
__device__ float g_P[(size_t)N_NODES * H4];
__device__ float g_Q[(size_t)N_NODES * H4];
__device__ int   g_idx64;
// W2^T hi/lo bf16, padded rows: [chunk][n=128][k=72 halfs]
__device__ __align__(16) unsigned short g_BH2[NCH * 128 * 72];
__device__ __align__(16) unsigned short g_BL2[NCH * 128 * 72];

typedef unsigned long long ull;
typedef unsigned int uint32;

// ---------------- helpers ----------------
__device__ __forceinline__ uint32 smem_u32(const void* p) {
    uint32 a; asm("{ .reg .u64 t; cvta.to.shared.u64 t, %1; cvt.u32.u64 %0, t; }"
                  : "=r"(a) : "l"(p)); return a;
}
__device__ __forceinline__ void ldsm4(uint32& r0, uint32& r1, uint32& r2, uint32& r3, uint32 addr) {
    asm volatile("ldmatrix.sync.aligned.m8n8.x4.shared.b16 {%0,%1,%2,%3}, [%4];"
                 : "=r"(r0), "=r"(r1), "=r"(r2), "=r"(r3) : "r"(addr));
}
__device__ __forceinline__ void mma16816(float* d, const uint32* a, uint32 b0, uint32 b1) {
    asm volatile("mma.sync.aligned.m16n8k16.row.col.f32.bf16.bf16.f32 "
                 "{%0,%1,%2,%3},{%4,%5,%6,%7},{%8,%9},{%0,%1,%2,%3};"
                 : "+f"(d[0]), "+f"(d[1]), "+f"(d[2]), "+f"(d[3])
                 : "r"(a[0]), "r"(a[1]), "r"(a[2]), "r"(a[3]), "r"(b0), "r"(b1));
}
__device__ __forceinline__ void cpasync16(uint32 dst, const void* src) {
    asm volatile("cp.async.cg.shared.global [%0], [%1], 16;" :: "r"(dst), "l"(src) : "memory");
}
#define CP_COMMIT() asm volatile("cp.async.commit_group;" ::: "memory")
#define CP_WAIT0()  asm volatile("cp.async.wait_group 0;" ::: "memory")

__device__ __forceinline__ uint32 cvt_bf16x2(float lo, float hi) {
    uint32 r; asm("cvt.rn.bf16x2.f32 %0, %1, %2;" : "=r"(r) : "f"(hi), "f"(lo)); return r;
}

// f32x2 helpers for pq_kernel
__device__ __forceinline__ ull pk2(float x, float y) {
    ull r; asm("mov.b64 %0, {%1, %2};" : "=l"(r) : "f"(x), "f"(y)); return r;
}
__device__ __forceinline__ void upk2(ull v, float& x, float& y) {
    asm("mov.b64 {%0, %1}, %2;" : "=f"(x), "=f"(y) : "l"(v));
}
__device__ __forceinline__ void fma2(ull& d, ull a, ull b) {
    asm("fma.rn.f32x2 %0, %1, %2, %0;" : "+l"(d) : "l"(a), "l"(b));
}

// ---------------------------------------------------------------------------
// Kernel 0: edge_index dtype detection (int64 vs silently-downcast int32)
// ---------------------------------------------------------------------------
__global__ void detect_kernel(const int* __restrict__ ei32)
{
    int t = threadIdx.x;
    int w = ei32[2 * t + 1];
    unsigned ballot = __ballot_sync(0xFFFFFFFFu, w != 0);
    __shared__ int any_nz;
    if (t == 0) any_nz = 0;
    __syncthreads();
    if ((t & 31) == 0 && ballot) atomicOr(&any_nz, 1);
    __syncthreads();
    if (t == 0) g_idx64 = any_nz ? 0 : 1;
}

// ---------------------------------------------------------------------------
// Kernel 0b: W2^T hi/lo bf16 split into padded [chunk][n][72] layout
// ---------------------------------------------------------------------------
__global__ void prep_w2(const float* __restrict__ W2)
{
    int i = blockIdx.x * 256 + threadIdx.x;   // 0..65535 = k*128+n
    int k = i >> 7, n = i & 127;
    float w = W2[i];
    __nv_bfloat16 hb = __float2bfloat16(w);
    float hf = __bfloat162float(hb);
    __nv_bfloat16 lb = __float2bfloat16(w - hf);
    int c = k >> 6, kl = k & 63;
    int idx = c * (128 * 72) + n * 72 + kl;
    g_BH2[idx] = __bfloat16_as_ushort(hb);
    g_BL2[idx] = __bfloat16_as_ushort(lb);
}

// ---------------------------------------------------------------------------
// Kernel 1: P/Q precompute (fp32 SIMT, f32x2) — unchanged
// ---------------------------------------------------------------------------
__global__ __launch_bounds__(256) void pq_kernel(
    const float* __restrict__ emb,
    const float* __restrict__ W1,
    const float* __restrict__ b1)
{
    __shared__ float A_s[64 * 36];
    __shared__ float B_s[32 * 128];

    const int t   = threadIdx.x;
    const int n0  = blockIdx.x * 64;
    const int j0t = blockIdx.y * 128;
    const int z   = blockIdx.z;
    float* gout = z ? g_Q : g_P;
    const float* Wbase = W1 + (size_t)z * HIDDEN * H4;

    ull acc[4][4];
#pragma unroll
    for (int i = 0; i < 4; i++)
#pragma unroll
        for (int p = 0; p < 4; p++) acc[i][p] = 0ull;

    const int e0 = (t >> 4) * 4;
    const int j0 = (t & 15) * 8;

    for (int kc = 0; kc < HIDDEN; kc += 32) {
#pragma unroll
        for (int i = 0; i < 2; i++) {
            int u  = t + i * 256;
            int nl = u >> 3;
            int k4 = (u & 7) * 4;
            int n  = n0 + nl; if (n >= N_NODES) n = N_NODES - 1;
            float4 v = *(const float4*)(emb + (size_t)n * HIDDEN + kc + k4);
            *(float4*)&A_s[nl * 36 + k4] = v;
        }
#pragma unroll
        for (int i = 0; i < 4; i++) {
            int f  = t + i * 256;
            int k  = f >> 5;
            int j4 = (f & 31) * 4;
            float4 v = *(const float4*)(Wbase + (size_t)(kc + k) * H4 + j0t + j4);
            *(float4*)&B_s[k * 128 + j4] = v;
        }
        __syncthreads();
#pragma unroll 8
        for (int kk = 0; kk < 32; kk++) {
            float4 bA = *(float4*)&B_s[kk * 128 + j0];
            float4 bB = *(float4*)&B_s[kk * 128 + j0 + 4];
            ull pb0 = pk2(bA.x, bA.y), pb1 = pk2(bA.z, bA.w);
            ull pb2 = pk2(bB.x, bB.y), pb3 = pk2(bB.z, bB.w);
#pragma unroll
            for (int i = 0; i < 4; i++) {
                float a = A_s[(e0 + i) * 36 + kk];
                ull pa = pk2(a, a);
                fma2(acc[i][0], pa, pb0);
                fma2(acc[i][1], pa, pb1);
                fma2(acc[i][2], pa, pb2);
                fma2(acc[i][3], pa, pb3);
            }
        }
        __syncthreads();
    }

#pragma unroll
    for (int i = 0; i < 4; i++) {
        int n = n0 + e0 + i;
        if (n < N_NODES) {
#pragma unroll
            for (int p = 0; p < 4; p++) {
                float x, y; upk2(acc[i][p], x, y);
                int j = j0t + j0 + p * 2;
                if (z == 0) { x += b1[j]; y += b1[j + 1]; }
                *(float2*)(&gout[(size_t)n * H4 + j]) = make_float2(x, y);
            }
        }
    }
}

// ---------------------------------------------------------------------------
// Kernel 2: warp-MMA edge kernel. M=256 edges x N=128 outs per block,
// 8 warps (32 rows each), K=512 in 8 chunks, 3-term bf16 split, double-buffered.
// SMEM layout: [0,HEAD) indices + b2/w3 | stage s at HEAD + s*STAGE.
// ---------------------------------------------------------------------------
__global__ __launch_bounds__(256, 1) void edge_mma_kernel(
    const void* __restrict__ ei,
    const float* __restrict__ b2,
    const float* __restrict__ W3,
    const float* __restrict__ b3,
    float* __restrict__ out)
{
    extern __shared__ char smem[];
    const uint32 sb = smem_u32(smem);
    int*   s_col = (int*)(smem);
    int*   s_row = (int*)(smem + 1024);
    float* s_b2  = (float*)(smem + 2048);
    float* s_w3  = (float*)(smem + 2560);

    const int t    = threadIdx.x;
    const int lane = t & 31;
    const int w    = t >> 5;
    const long long eb = (long long)blockIdx.x * TILE_M;

    {
        int c, r;
        if (g_idx64) {
            const long long* p = (const long long*)ei;
            c = (int)p[eb + t]; r = (int)p[(long long)N_EDGES + eb + t];
        } else {
            const int* p = (const int*)ei;
            c = p[eb + t]; r = p[N_EDGES + eb + t];
        }
        c = min(max(c, 0), N_NODES - 1);
        r = min(max(r, 0), N_NODES - 1);
        s_col[t] = c; s_row[t] = r;
        if (t < 128) { s_b2[t] = b2[t]; s_w3[t] = W3[t]; }
    }
    __syncthreads();

    // A gather mapping: 2 threads per edge, 2 passes of 128 edges
    const int el = t >> 1;
    const int h  = t & 1;
    size_t colOff[2], rowOff[2];
    uint32 aStore[2];
#pragma unroll
    for (int pp = 0; pp < 2; pp++) {
        int e2 = pp * 128 + el;
        colOff[pp] = (size_t)s_col[e2] * H4 + (size_t)h * 32;
        rowOff[pp] = (size_t)s_row[e2] * H4 + (size_t)h * 32;
        aStore[pp] = (uint32)e2 * ROWB + (uint32)h * 64;   // relative to stage A base
    }

    // ldmatrix lane offsets (relative to stage base)
    const uint32 aLd0 = (uint32)(w * 32 + (lane & 15)) * ROWB + (uint32)(lane >> 4) * 16;
    const uint32 aLd1 = aLd0 + 16 * ROWB;
    const uint32 bRow = (uint32)((lane & 7) + ((lane >> 4) << 3));
    const uint32 bLd  = bRow * ROWB + (uint32)((lane >> 3) & 1) * 16;

    float acc[2][16][4];
#pragma unroll
    for (int rb = 0; rb < 2; rb++)
#pragma unroll
        for (int nb = 0; nb < 16; nb++)
#pragma unroll
            for (int q = 0; q < 4; q++) acc[rb][nb][q] = 0.f;

    // ---- build A tile (relu(P+Q) hi/lo bf16) into stage stg ----
    auto buildA = [&](int chunk, int stg) {
        char* base = smem + HEAD + (size_t)stg * STAGE;
        char* AH = base + A_OFF_H;
        char* AL = base + A_OFF_L;
#pragma unroll
        for (int pp = 0; pp < 2; pp++) {
            const float4* pr = (const float4*)(g_P + colOff[pp] + chunk * KC);
            const float4* qr = (const float4*)(g_Q + rowOff[pp] + chunk * KC);
#pragma unroll
            for (int g = 0; g < 4; g++) {
                float4 p0 = pr[2 * g], p1 = pr[2 * g + 1];
                float4 q0 = qr[2 * g], q1 = qr[2 * g + 1];
                float a0 = fmaxf(p0.x + q0.x, 0.f), a1 = fmaxf(p0.y + q0.y, 0.f);
                float a2 = fmaxf(p0.z + q0.z, 0.f), a3 = fmaxf(p0.w + q0.w, 0.f);
                float a4 = fmaxf(p1.x + q1.x, 0.f), a5 = fmaxf(p1.y + q1.y, 0.f);
                float a6 = fmaxf(p1.z + q1.z, 0.f), a7 = fmaxf(p1.w + q1.w, 0.f);
                uint32 h01 = cvt_bf16x2(a0, a1), h23 = cvt_bf16x2(a2, a3);
                uint32 h45 = cvt_bf16x2(a4, a5), h67 = cvt_bf16x2(a6, a7);
                float f0 = __uint_as_float(h01 << 16), f1 = __uint_as_float(h01 & 0xFFFF0000u);
                float f2 = __uint_as_float(h23 << 16), f3 = __uint_as_float(h23 & 0xFFFF0000u);
                float f4 = __uint_as_float(h45 << 16), f5 = __uint_as_float(h45 & 0xFFFF0000u);
                float f6 = __uint_as_float(h67 << 16), f7 = __uint_as_float(h67 & 0xFFFF0000u);
                uint32 l01 = cvt_bf16x2(a0 - f0, a1 - f1), l23 = cvt_bf16x2(a2 - f2, a3 - f3);
                uint32 l45 = cvt_bf16x2(a4 - f4, a5 - f5), l67 = cvt_bf16x2(a6 - f6, a7 - f7);
                uint32 o = aStore[pp] + g * 16;
                *(uint4*)(AH + o) = make_uint4(h01, h23, h45, h67);
                *(uint4*)(AL + o) = make_uint4(l01, l23, l45, l67);
            }
        }
    };
    // ---- stream B chunk into stage stg via cp.async ----
    auto loadB = [&](int chunk, int stg) {
        const uint4* srcH = (const uint4*)g_BH2 + chunk * 1152;
        const uint4* srcL = (const uint4*)g_BL2 + chunk * 1152;
        uint32 bw = sb + HEAD + (uint32)stg * STAGE;
        for (int u = t; u < 1152; u += 256) {
            cpasync16(bw + B_OFF_H + u * 16, srcH + u);
            cpasync16(bw + B_OFF_L + u * 16, srcL + u);
        }
        CP_COMMIT();
    };

    // ---------------- prologue: stage chunk 0 into buffer 0 ----------------
    loadB(0, 0);
    buildA(0, 0);
    CP_WAIT0();
    __syncthreads();

    // ---------------- main loop ----------------
    for (int i = 0; i < NCH; i++) {
        const int s = i & 1;
        const uint32 bufR = sb + HEAD + (uint32)s * STAGE;

        if (i + 1 < NCH) {
            loadB(i + 1, s ^ 1);
            buildA(i + 1, s ^ 1);
        }

        // MMA phase on buffer s
#pragma unroll
        for (int ks = 0; ks < 4; ks++) {
            const uint32 kb = (uint32)ks * 32;
            uint32 ah0[4], ah1[4], al0[4], al1[4];
            ldsm4(ah0[0], ah0[1], ah0[2], ah0[3], bufR + A_OFF_H + aLd0 + kb);
            ldsm4(ah1[0], ah1[1], ah1[2], ah1[3], bufR + A_OFF_H + aLd1 + kb);
            ldsm4(al0[0], al0[1], al0[2], al0[3], bufR + A_OFF_L + aLd0 + kb);
            ldsm4(al1[0], al1[1], al1[2], al1[3], bufR + A_OFF_L + aLd1 + kb);
#pragma unroll
            for (int p = 0; p < 8; p++) {
                uint32 r0, r1, r2, r3;
                ldsm4(r0, r1, r2, r3, bufR + B_OFF_H + bLd + (uint32)p * (16 * ROWB) + kb);
                mma16816(acc[0][2 * p],     ah0, r0, r1);
                mma16816(acc[0][2 * p + 1], ah0, r2, r3);
                mma16816(acc[1][2 * p],     ah1, r0, r1);
                mma16816(acc[1][2 * p + 1], ah1, r2, r3);
                mma16816(acc[0][2 * p],     al0, r0, r1);
                mma16816(acc[0][2 * p + 1], al0, r2, r3);
                mma16816(acc[1][2 * p],     al1, r0, r1);
                mma16816(acc[1][2 * p + 1], al1, r2, r3);
                ldsm4(r0, r1, r2, r3, bufR + B_OFF_L + bLd + (uint32)p * (16 * ROWB) + kb);
                mma16816(acc[0][2 * p],     ah0, r0, r1);
                mma16816(acc[0][2 * p + 1], ah0, r2, r3);
                mma16816(acc[1][2 * p],     ah1, r0, r1);
                mma16816(acc[1][2 * p + 1], ah1, r2, r3);
            }
        }
        CP_WAIT0();
        __syncthreads();
    }

    // ---------------- epilogue: fold layer 3 ----------------
    const int g4 = lane >> 2;
    const int t4 = lane & 3;
    const float b3v = b3[0];
#pragma unroll
    for (int rb = 0; rb < 2; rb++) {
        float sA = 0.f, sB = 0.f;
#pragma unroll
        for (int nb = 0; nb < 16; nb++) {
            int c0 = nb * 8 + 2 * t4;
            int c1 = c0 + 1;
            sA += fmaxf(acc[rb][nb][0] + s_b2[c0], 0.f) * s_w3[c0];
            sA += fmaxf(acc[rb][nb][1] + s_b2[c1], 0.f) * s_w3[c1];
            sB += fmaxf(acc[rb][nb][2] + s_b2[c0], 0.f) * s_w3[c0];
            sB += fmaxf(acc[rb][nb][3] + s_b2[c1], 0.f) * s_w3[c1];
        }
        sA += __shfl_xor_sync(0xFFFFFFFFu, sA, 1);
        sA += __shfl_xor_sync(0xFFFFFFFFu, sA, 2);
        sB += __shfl_xor_sync(0xFFFFFFFFu, sB, 1);
        sB += __shfl_xor_sync(0xFFFFFFFFu, sB, 2);
        if (t4 == 0) {
            long long rA = eb + w * 32 + rb * 16 + g4;
            out[rA]     = sA + b3v;
            out[rA + 8] = sB + b3v;
        }
    }
}

extern "C" void kernel_launch(void* const* d_in, const int* in_sizes, int n_in,
                              void* d_out, int out_size)
{
    const float* emb = (const float*)d_in[0];
    const void*  ei  = d_in[1];
    const float* W1  = (const float*)d_in[2];
    const float* b1  = (const float*)d_in[3];
    const float* W2  = (const float*)d_in[4];
    const float* b2  = (const float*)d_in[5];
    const float* W3  = (const float*)d_in[6];
    const float* b3  = (const float*)d_in[7];
    float* out = (float*)d_out;
    (void)in_sizes; (void)n_in; (void)out_size;

    cudaFuncSetAttribute(edge_mma_kernel,
                         cudaFuncAttributeMaxDynamicSharedMemorySize, SMEM_BYTES);

    detect_kernel<<<1, 128>>>((const int*)ei);
    prep_w2<<<256, 256>>>(W2);
    dim3 g1((N_NODES + 63) / 64, H4 / 128, 2);
    pq_kernel<<<g1, 256>>>(emb, W1, b1);
    edge_mma_kernel<<<EDGE_BLOCKS, 256, SMEM_BYTES>>>(ei, b2, W3, b3, out);
}

// round 7
// speedup vs baseline: 1.4069x; 1.4069x over previous
#include <cuda_runtime.h>
#include <cuda_bf16.h>
#include <cstdint>

#define N_NODES 50000
#define N_EDGES 800000
#define HIDDEN  128
#define H4      512
#define KC      64            // K elements per chunk
#define NCH     8             // 512 / 64
#define TILE_M  128
#define EDGE_BLOCKS (N_EDGES / TILE_M)   // 6250

#define ROWB    144                // padded bytes per 64-half tile row
#define A_OFF_H 0
#define A_OFF_L 18432              // 128*144
#define B_OFF_H 36864
#define B_OFF_L 55296
#define STAGE   73728
#define HEAD    4096
#define SMEM_BYTES (HEAD + 2 * STAGE)   // 151552

// Precomputed P = emb @ W1[:128] + b1, Q = emb @ W1[128:]
__device__ float g_P[(size_t)N_NODES * H4];
__device__ float g_Q[(size_t)N_NODES * H4];
__device__ int   g_idx64;
// W2^T hi/lo bf16, padded rows: [chunk][n=128][k=72 halfs]
__device__ __align__(16) unsigned short g_BH2[NCH * 128 * 72];
__device__ __align__(16) unsigned short g_BL2[NCH * 128 * 72];

typedef unsigned long long ull;
typedef unsigned int uint32;

// ---------------- helpers ----------------
__device__ __forceinline__ uint32 smem_u32(const void* p) {
    uint32 a; asm("{ .reg .u64 t; cvta.to.shared.u64 t, %1; cvt.u32.u64 %0, t; }"
                  : "=r"(a) : "l"(p)); return a;
}
__device__ __forceinline__ void ldsm4(uint32& r0, uint32& r1, uint32& r2, uint32& r3, uint32 addr) {
    asm volatile("ldmatrix.sync.aligned.m8n8.x4.shared.b16 {%0,%1,%2,%3}, [%4];"
                 : "=r"(r0), "=r"(r1), "=r"(r2), "=r"(r3) : "r"(addr));
}
__device__ __forceinline__ void mma16816(float* d, const uint32* a, uint32 b0, uint32 b1) {
    asm volatile("mma.sync.aligned.m16n8k16.row.col.f32.bf16.bf16.f32 "
                 "{%0,%1,%2,%3},{%4,%5,%6,%7},{%8,%9},{%0,%1,%2,%3};"
                 : "+f"(d[0]), "+f"(d[1]), "+f"(d[2]), "+f"(d[3])
                 : "r"(a[0]), "r"(a[1]), "r"(a[2]), "r"(a[3]), "r"(b0), "r"(b1));
}
__device__ __forceinline__ void cpasync16(uint32 dst, const void* src) {
    asm volatile("cp.async.cg.shared.global [%0], [%1], 16;" :: "r"(dst), "l"(src) : "memory");
}
#define CP_COMMIT() asm volatile("cp.async.commit_group;" ::: "memory")
#define CP_WAIT0()  asm volatile("cp.async.wait_group 0;" ::: "memory")

__device__ __forceinline__ uint32 cvt_bf16x2(float lo, float hi) {
    uint32 r; asm("cvt.rn.bf16x2.f32 %0, %1, %2;" : "=r"(r) : "f"(hi), "f"(lo)); return r;
}

// f32x2 helpers for pq_kernel
__device__ __forceinline__ ull pk2(float x, float y) {
    ull r; asm("mov.b64 %0, {%1, %2};" : "=l"(r) : "f"(x), "f"(y)); return r;
}
__device__ __forceinline__ void upk2(ull v, float& x, float& y) {
    asm("mov.b64 {%0, %1}, %2;" : "=f"(x), "=f"(y) : "l"(v));
}
__device__ __forceinline__ void fma2(ull& d, ull a, ull b) {
    asm("fma.rn.f32x2 %0, %1, %2, %0;" : "+l"(d) : "l"(a), "l"(b));
}

// ---------------------------------------------------------------------------
// Kernel 0: edge_index dtype detection (int64 vs silently-downcast int32)
// ---------------------------------------------------------------------------
__global__ void detect_kernel(const int* __restrict__ ei32)
{
    int t = threadIdx.x;
    int w = ei32[2 * t + 1];
    unsigned ballot = __ballot_sync(0xFFFFFFFFu, w != 0);
    __shared__ int any_nz;
    if (t == 0) any_nz = 0;
    __syncthreads();
    if ((t & 31) == 0 && ballot) atomicOr(&any_nz, 1);
    __syncthreads();
    if (t == 0) g_idx64 = any_nz ? 0 : 1;
}

// ---------------------------------------------------------------------------
// Kernel 0b: W2^T hi/lo bf16 split into padded [chunk][n][72] layout
// ---------------------------------------------------------------------------
__global__ void prep_w2(const float* __restrict__ W2)
{
    int i = blockIdx.x * 256 + threadIdx.x;   // 0..65535 = k*128+n
    int k = i >> 7, n = i & 127;
    float w = W2[i];
    __nv_bfloat16 hb = __float2bfloat16(w);
    float hf = __bfloat162float(hb);
    __nv_bfloat16 lb = __float2bfloat16(w - hf);
    int c = k >> 6, kl = k & 63;
    int idx = c * (128 * 72) + n * 72 + kl;
    g_BH2[idx] = __bfloat16_as_ushort(hb);
    g_BL2[idx] = __bfloat16_as_ushort(lb);
}

// ---------------------------------------------------------------------------
// Kernel 1: P/Q precompute (fp32 SIMT, f32x2) — unchanged
// ---------------------------------------------------------------------------
__global__ __launch_bounds__(256) void pq_kernel(
    const float* __restrict__ emb,
    const float* __restrict__ W1,
    const float* __restrict__ b1)
{
    __shared__ float A_s[64 * 36];
    __shared__ float B_s[32 * 128];

    const int t   = threadIdx.x;
    const int n0  = blockIdx.x * 64;
    const int j0t = blockIdx.y * 128;
    const int z   = blockIdx.z;
    float* gout = z ? g_Q : g_P;
    const float* Wbase = W1 + (size_t)z * HIDDEN * H4;

    ull acc[4][4];
#pragma unroll
    for (int i = 0; i < 4; i++)
#pragma unroll
        for (int p = 0; p < 4; p++) acc[i][p] = 0ull;

    const int e0 = (t >> 4) * 4;
    const int j0 = (t & 15) * 8;

    for (int kc = 0; kc < HIDDEN; kc += 32) {
#pragma unroll
        for (int i = 0; i < 2; i++) {
            int u  = t + i * 256;
            int nl = u >> 3;
            int k4 = (u & 7) * 4;
            int n  = n0 + nl; if (n >= N_NODES) n = N_NODES - 1;
            float4 v = *(const float4*)(emb + (size_t)n * HIDDEN + kc + k4);
            *(float4*)&A_s[nl * 36 + k4] = v;
        }
#pragma unroll
        for (int i = 0; i < 4; i++) {
            int f  = t + i * 256;
            int k  = f >> 5;
            int j4 = (f & 31) * 4;
            float4 v = *(const float4*)(Wbase + (size_t)(kc + k) * H4 + j0t + j4);
            *(float4*)&B_s[k * 128 + j4] = v;
        }
        __syncthreads();
#pragma unroll 8
        for (int kk = 0; kk < 32; kk++) {
            float4 bA = *(float4*)&B_s[kk * 128 + j0];
            float4 bB = *(float4*)&B_s[kk * 128 + j0 + 4];
            ull pb0 = pk2(bA.x, bA.y), pb1 = pk2(bA.z, bA.w);
            ull pb2 = pk2(bB.x, bB.y), pb3 = pk2(bB.z, bB.w);
#pragma unroll
            for (int i = 0; i < 4; i++) {
                float a = A_s[(e0 + i) * 36 + kk];
                ull pa = pk2(a, a);
                fma2(acc[i][0], pa, pb0);
                fma2(acc[i][1], pa, pb1);
                fma2(acc[i][2], pa, pb2);
                fma2(acc[i][3], pa, pb3);
            }
        }
        __syncthreads();
    }

#pragma unroll
    for (int i = 0; i < 4; i++) {
        int n = n0 + e0 + i;
        if (n < N_NODES) {
#pragma unroll
            for (int p = 0; p < 4; p++) {
                float x, y; upk2(acc[i][p], x, y);
                int j = j0t + j0 + p * 2;
                if (z == 0) { x += b1[j]; y += b1[j + 1]; }
                *(float2*)(&gout[(size_t)n * H4 + j]) = make_float2(x, y);
            }
        }
    }
}

// ---------------------------------------------------------------------------
// Kernel 2: warp-MMA edge kernel. M=128 edges x N=128 outs per block.
// 8 warps in 4(M) x 2(N): each warp computes 32 rows x 64 cols.
// K=512 in 8 chunks, 3-term bf16 split, double-buffered.
// ---------------------------------------------------------------------------
__global__ __launch_bounds__(256, 1) void edge_mma_kernel(
    const void* __restrict__ ei,
    const float* __restrict__ b2,
    const float* __restrict__ W3,
    const float* __restrict__ b3,
    float* __restrict__ out)
{
    extern __shared__ char smem[];
    const uint32 sb = smem_u32(smem);
    int*   s_col = (int*)(smem);             // 512 B
    int*   s_row = (int*)(smem + 512);       // 512 B
    float* s_b2  = (float*)(smem + 1024);    // 512 B
    float* s_w3  = (float*)(smem + 1536);    // 512 B
    float* s_red = (float*)(smem + 2048);    // 1024 B (2 x 128 floats)

    const int t    = threadIdx.x;
    const int lane = t & 31;
    const int w    = t >> 5;
    const int wm   = w & 3;        // M block (rows wm*32)
    const int wn   = w >> 2;       // N block (cols wn*64)
    const long long eb = (long long)blockIdx.x * TILE_M;

    if (t < 128) {
        int c, r;
        if (g_idx64) {
            const long long* p = (const long long*)ei;
            c = (int)p[eb + t]; r = (int)p[(long long)N_EDGES + eb + t];
        } else {
            const int* p = (const int*)ei;
            c = p[eb + t]; r = p[N_EDGES + eb + t];
        }
        c = min(max(c, 0), N_NODES - 1);
        r = min(max(r, 0), N_NODES - 1);
        s_col[t] = c; s_row[t] = r;
    } else {
        int j = t - 128;
        s_b2[j] = b2[j]; s_w3[j] = W3[j];
    }
    __syncthreads();

    // A gather mapping: 2 threads per edge (128 edges)
    const int el = t >> 1;
    const int h  = t & 1;
    const size_t colOff = (size_t)s_col[el] * H4 + (size_t)h * 32;
    const size_t rowOff = (size_t)s_row[el] * H4 + (size_t)h * 32;
    const uint32 aStore = (uint32)el * ROWB + (uint32)h * 64;

    // ldmatrix lane offsets (relative to stage base)
    const uint32 aLd0 = (uint32)(wm * 32 + (lane & 15)) * ROWB + (uint32)(lane >> 4) * 16;
    const uint32 aLd1 = aLd0 + 16 * ROWB;
    const uint32 bRow = (uint32)((lane & 7) + ((lane >> 4) << 3));
    const uint32 bLd  = ((uint32)wn * 64 + bRow) * ROWB + (uint32)((lane >> 3) & 1) * 16;

    // acc[rb][nb][4]: rb = 16-row sub-block (2), nb = 8-col block (8) -> 64 regs
    float acc[2][8][4];
#pragma unroll
    for (int rb = 0; rb < 2; rb++)
#pragma unroll
        for (int nb = 0; nb < 8; nb++)
#pragma unroll
            for (int q = 0; q < 4; q++) acc[rb][nb][q] = 0.f;

    // ---- build A tile (relu(P+Q) hi/lo bf16) into stage stg ----
    auto buildA = [&](int chunk, int stg) {
        char* base = smem + HEAD + (size_t)stg * STAGE;
        char* AH = base + A_OFF_H;
        char* AL = base + A_OFF_L;
        const float4* pr = (const float4*)(g_P + colOff + chunk * KC);
        const float4* qr = (const float4*)(g_Q + rowOff + chunk * KC);
#pragma unroll
        for (int g = 0; g < 4; g++) {
            float4 p0 = pr[2 * g], p1 = pr[2 * g + 1];
            float4 q0 = qr[2 * g], q1 = qr[2 * g + 1];
            float a0 = fmaxf(p0.x + q0.x, 0.f), a1 = fmaxf(p0.y + q0.y, 0.f);
            float a2 = fmaxf(p0.z + q0.z, 0.f), a3 = fmaxf(p0.w + q0.w, 0.f);
            float a4 = fmaxf(p1.x + q1.x, 0.f), a5 = fmaxf(p1.y + q1.y, 0.f);
            float a6 = fmaxf(p1.z + q1.z, 0.f), a7 = fmaxf(p1.w + q1.w, 0.f);
            uint32 h01 = cvt_bf16x2(a0, a1), h23 = cvt_bf16x2(a2, a3);
            uint32 h45 = cvt_bf16x2(a4, a5), h67 = cvt_bf16x2(a6, a7);
            float f0 = __uint_as_float(h01 << 16), f1 = __uint_as_float(h01 & 0xFFFF0000u);
            float f2 = __uint_as_float(h23 << 16), f3 = __uint_as_float(h23 & 0xFFFF0000u);
            float f4 = __uint_as_float(h45 << 16), f5 = __uint_as_float(h45 & 0xFFFF0000u);
            float f6 = __uint_as_float(h67 << 16), f7 = __uint_as_float(h67 & 0xFFFF0000u);
            uint32 l01 = cvt_bf16x2(a0 - f0, a1 - f1), l23 = cvt_bf16x2(a2 - f2, a3 - f3);
            uint32 l45 = cvt_bf16x2(a4 - f4, a5 - f5), l67 = cvt_bf16x2(a6 - f6, a7 - f7);
            uint32 o = aStore + g * 16;
            *(uint4*)(AH + o) = make_uint4(h01, h23, h45, h67);
            *(uint4*)(AL + o) = make_uint4(l01, l23, l45, l67);
        }
    };
    // ---- stream B chunk into stage stg via cp.async ----
    auto loadB = [&](int chunk, int stg) {
        const uint4* srcH = (const uint4*)g_BH2 + chunk * 1152;
        const uint4* srcL = (const uint4*)g_BL2 + chunk * 1152;
        uint32 bw = sb + HEAD + (uint32)stg * STAGE;
        for (int u = t; u < 1152; u += 256) {
            cpasync16(bw + B_OFF_H + u * 16, srcH + u);
            cpasync16(bw + B_OFF_L + u * 16, srcL + u);
        }
        CP_COMMIT();
    };

    // ---------------- prologue ----------------
    loadB(0, 0);
    buildA(0, 0);
    CP_WAIT0();
    __syncthreads();

    // ---------------- main loop ----------------
    for (int i = 0; i < NCH; i++) {
        const int s = i & 1;
        const uint32 bufR = sb + HEAD + (uint32)s * STAGE;

        if (i + 1 < NCH) {
            loadB(i + 1, s ^ 1);
            buildA(i + 1, s ^ 1);
        }

        // MMA phase on buffer s (this warp: rows wm*32..+31, cols wn*64..+63)
#pragma unroll
        for (int ks = 0; ks < 4; ks++) {
            const uint32 kb = (uint32)ks * 32;
            uint32 ah0[4], ah1[4], al0[4], al1[4];
            ldsm4(ah0[0], ah0[1], ah0[2], ah0[3], bufR + A_OFF_H + aLd0 + kb);
            ldsm4(ah1[0], ah1[1], ah1[2], ah1[3], bufR + A_OFF_H + aLd1 + kb);
            ldsm4(al0[0], al0[1], al0[2], al0[3], bufR + A_OFF_L + aLd0 + kb);
            ldsm4(al1[0], al1[1], al1[2], al1[3], bufR + A_OFF_L + aLd1 + kb);
#pragma unroll
            for (int p = 0; p < 4; p++) {
                uint32 r0, r1, r2, r3;
                ldsm4(r0, r1, r2, r3, bufR + B_OFF_H + bLd + (uint32)p * (16 * ROWB) + kb);
                mma16816(acc[0][2 * p],     ah0, r0, r1);
                mma16816(acc[0][2 * p + 1], ah0, r2, r3);
                mma16816(acc[1][2 * p],     ah1, r0, r1);
                mma16816(acc[1][2 * p + 1], ah1, r2, r3);
                mma16816(acc[0][2 * p],     al0, r0, r1);
                mma16816(acc[0][2 * p + 1], al0, r2, r3);
                mma16816(acc[1][2 * p],     al1, r0, r1);
                mma16816(acc[1][2 * p + 1], al1, r2, r3);
                ldsm4(r0, r1, r2, r3, bufR + B_OFF_L + bLd + (uint32)p * (16 * ROWB) + kb);
                mma16816(acc[0][2 * p],     ah0, r0, r1);
                mma16816(acc[0][2 * p + 1], ah0, r2, r3);
                mma16816(acc[1][2 * p],     ah1, r0, r1);
                mma16816(acc[1][2 * p + 1], ah1, r2, r3);
            }
        }
        CP_WAIT0();
        __syncthreads();
    }

    // ---------------- epilogue: fold layer 3, cross-warp N reduce ----------------
    const int g4 = lane >> 2;
    const int t4 = lane & 3;
#pragma unroll
    for (int rb = 0; rb < 2; rb++) {
        float sA = 0.f, sB = 0.f;
#pragma unroll
        for (int nb = 0; nb < 8; nb++) {
            int c0 = wn * 64 + nb * 8 + 2 * t4;
            int c1 = c0 + 1;
            sA += fmaxf(acc[rb][nb][0] + s_b2[c0], 0.f) * s_w3[c0];
            sA += fmaxf(acc[rb][nb][1] + s_b2[c1], 0.f) * s_w3[c1];
            sB += fmaxf(acc[rb][nb][2] + s_b2[c0], 0.f) * s_w3[c0];
            sB += fmaxf(acc[rb][nb][3] + s_b2[c1], 0.f) * s_w3[c1];
        }
        sA += __shfl_xor_sync(0xFFFFFFFFu, sA, 1);
        sA += __shfl_xor_sync(0xFFFFFFFFu, sA, 2);
        sB += __shfl_xor_sync(0xFFFFFFFFu, sB, 1);
        sB += __shfl_xor_sync(0xFFFFFFFFu, sB, 2);
        if (t4 == 0) {
            int row = wm * 32 + rb * 16 + g4;
            s_red[wn * 128 + row]     = sA;
            s_red[wn * 128 + row + 8] = sB;
        }
    }
    __syncthreads();
    if (t < 128) {
        out[eb + t] = s_red[t] + s_red[128 + t] + b3[0];
    }
}

extern "C" void kernel_launch(void* const* d_in, const int* in_sizes, int n_in,
                              void* d_out, int out_size)
{
    const float* emb = (const float*)d_in[0];
    const void*  ei  = d_in[1];
    const float* W1  = (const float*)d_in[2];
    const float* b1  = (const float*)d_in[3];
    const float* W2  = (const float*)d_in[4];
    const float* b2  = (const float*)d_in[5];
    const float* W3  = (const float*)d_in[6];
    const float* b3  = (const float*)d_in[7];
    float* out = (float*)d_out;
    (void)in_sizes; (void)n_in; (void)out_size;

    cudaFuncSetAttribute(edge_mma_kernel,
                         cudaFuncAttributeMaxDynamicSharedMemorySize, SMEM_BYTES);

    detect_kernel<<<1, 128>>>((const int*)ei);
    prep_w2<<<256, 256>>>(W2);
    dim3 g1((N_NODES + 63) / 64, H4 / 128, 2);
    pq_kernel<<<g1, 256>>>(emb, W1, b1);
    edge_mma_kernel<<<EDGE_BLOCKS, 256, SMEM_BYTES>>>(ei, b2, W3, b3, out);
}